// round 17
// baseline (speedup 1.0000x reference)
#include <cuda_runtime.h>
#include <cuda_bf16.h>
#include <cstdint>
#include <cstddef>

#define SEQ 2048
#define DIM 1024
#define NH 16
#define HD 64
#define ROWS 16
#define SCP 2052

#define QSP 144
#define OFF_KH 0
#define OFF_KM 18432
#define OFF_KL 36864

// Scratch (allocation-free rule: __device__ globals)
__device__ __nv_bfloat16 g_qh[SEQ * DIM], g_qm[SEQ * DIM], g_ql[SEQ * DIM];
__device__ __nv_bfloat16 g_kh[SEQ * DIM], g_km[SEQ * DIM], g_kl[SEQ * DIM];
__device__ __nv_bfloat16 g_vth[DIM * SEQ], g_vtm[DIM * SEQ];
__device__ __nv_bfloat16 g_xh[SEQ * DIM], g_xm[SEQ * DIM];
__device__ __nv_bfloat16 g_aoh[SEQ * DIM], g_aom[SEQ * DIM];
__device__ __nv_bfloat16 g_wvh[DIM * DIM], g_wvm[DIM * DIM];
__device__ __nv_bfloat16 g_woh[DIM * DIM], g_wom[DIM * DIM];
// entmax weights P, per head, bf16 h/m (zero-padded per row to its 128-block)
__device__ __nv_bfloat16 g_ph[(size_t)NH * SEQ * SEQ];
__device__ __nv_bfloat16 g_pm[(size_t)NH * SEQ * SEQ];

// ===========================================================================
// Helpers
// ===========================================================================
__device__ __forceinline__ uint32_t smem_u32(const void* p) {
    uint32_t a;
    asm("{ .reg .u64 t; cvta.to.shared.u64 t, %1; cvt.u32.u64 %0, t; }"
        : "=r"(a) : "l"(p));
    return a;
}
__device__ __forceinline__ void ldsm4(uint32_t* r, uint32_t addr) {
    asm volatile("ldmatrix.sync.aligned.m8n8.x4.shared.b16 {%0,%1,%2,%3}, [%4];"
                 : "=r"(r[0]), "=r"(r[1]), "=r"(r[2]), "=r"(r[3]) : "r"(addr));
}
__device__ __forceinline__ void mma16816(float* c, const uint32_t* a, const uint32_t* b) {
    asm volatile(
        "mma.sync.aligned.m16n8k16.row.col.f32.bf16.bf16.f32 "
        "{%0,%1,%2,%3}, {%4,%5,%6,%7}, {%8,%9}, {%0,%1,%2,%3};"
        : "+f"(c[0]), "+f"(c[1]), "+f"(c[2]), "+f"(c[3])
        : "r"(a[0]), "r"(a[1]), "r"(a[2]), "r"(a[3]), "r"(b[0]), "r"(b[1]));
}
__device__ __forceinline__ void cp16(uint32_t s, const void* g) {
    asm volatile("cp.async.ca.shared.global [%0], [%1], 16;" :: "r"(s), "l"(g));
}
__device__ __forceinline__ uint32_t bf2h(float2 v) {
    __nv_bfloat162 b = __floats2bfloat162_rn(v.x, v.y);
    return *(uint32_t*)&b;
}
__device__ __forceinline__ uint32_t bf2m(float2 v, uint32_t hbits) {
    __nv_bfloat162 h = *(__nv_bfloat162*)&hbits;
    return bf2h(make_float2(v.x - __bfloat162float(h.x),
                            v.y - __bfloat162float(h.y)));
}
__device__ __forceinline__ void split3_f2(float2 v, uint32_t& H, uint32_t& M, uint32_t& L) {
    H = bf2h(v);
    __nv_bfloat162 h2 = *(__nv_bfloat162*)&H;
    float2 r1 = make_float2(v.x - __bfloat162float(h2.x),
                            v.y - __bfloat162float(h2.y));
    M = bf2h(r1);
    __nv_bfloat162 m2 = *(__nv_bfloat162*)&M;
    float2 r2 = make_float2(r1.x - __bfloat162float(m2.x),
                            r1.y - __bfloat162float(m2.y));
    L = bf2h(r2);
}

// ===========================================================================
// Split fp32 -> 2x bf16
// ===========================================================================
__global__ __launch_bounds__(256) void split2(
    const float* __restrict__ in, __nv_bfloat16* __restrict__ h,
    __nv_bfloat16* __restrict__ m, int n4)
{
    int i = blockIdx.x * 256 + threadIdx.x;
    if (i >= n4) return;
    float4 v = ((const float4*)in)[i];
    uint32_t H0, M0, H1, M1;
    H0 = bf2h(make_float2(v.x, v.y)); M0 = bf2m(make_float2(v.x, v.y), H0);
    H1 = bf2h(make_float2(v.z, v.w)); M1 = bf2m(make_float2(v.z, v.w), H1);
    ((uint32_t*)h)[i * 2 + 0] = H0; ((uint32_t*)h)[i * 2 + 1] = H1;
    ((uint32_t*)m)[i * 2 + 0] = M0; ((uint32_t*)m)[i * 2 + 1] = M1;
}

// ===========================================================================
// fp32 SIMT SGEMM for Q,K (fp32-faithful; REQUIRED for entmax flip safety).
// Epilogue writes bf16 h/m/l triples (0.125 folded for Q, exact).
// ===========================================================================
__global__ __launch_bounds__(256, 2) void sgemm_split(
    const float* __restrict__ A,
    const float* __restrict__ Bq, const float* __restrict__ Bk,
    __nv_bfloat16* __restrict__ qh, __nv_bfloat16* __restrict__ qm,
    __nv_bfloat16* __restrict__ ql,
    __nv_bfloat16* __restrict__ kh, __nv_bfloat16* __restrict__ km,
    __nv_bfloat16* __restrict__ kl,
    int Kdim, int Ndim)
{
    const int z = blockIdx.z;
    const float* B = z ? Bk : Bq;
    __nv_bfloat16* oh = z ? kh : qh;
    __nv_bfloat16* om = z ? km : qm;
    __nv_bfloat16* ol = z ? kl : ql;
    const float scl = z ? 1.0f : 0.125f;

    __shared__ __align__(16) float As[2][8][128];
    __shared__ __align__(16) float Bs[2][8][128];

    const int tid = threadIdx.x;
    const int m0 = blockIdx.y * 128;
    const int n0 = blockIdx.x * 128;
    const float* Ab = A + (size_t)m0 * Kdim;
    const float* Bb = B + (size_t)n0 * Kdim;

    const int lr = tid >> 1;
    const int lk = (tid & 1) * 4;

    const int warp = tid >> 5, lane = tid & 31;
    const int tr = (warp & 3) * 32 + (lane & 3) * 8;
    const int tc = (warp >> 2) * 64 + (lane >> 2) * 8;

    float acc[8][8];
#pragma unroll
    for (int i = 0; i < 8; i++)
#pragma unroll
        for (int j = 0; j < 8; j++) acc[i][j] = 0.f;

    const int NC = Kdim >> 3;
    for (int c = 0; c < NC; c++) {
        const int s = c & 1;
        const int k0 = c << 3;
        float4 a4 = *(const float4*)(Ab + (size_t)lr * Kdim + k0 + lk);
        float4 b4 = *(const float4*)(Bb + (size_t)lr * Kdim + k0 + lk);
        As[s][lk + 0][lr] = a4.x; As[s][lk + 1][lr] = a4.y;
        As[s][lk + 2][lr] = a4.z; As[s][lk + 3][lr] = a4.w;
        Bs[s][lk + 0][lr] = b4.x; Bs[s][lk + 1][lr] = b4.y;
        Bs[s][lk + 2][lr] = b4.z; Bs[s][lk + 3][lr] = b4.w;
        __syncthreads();
#pragma unroll
        for (int kk = 0; kk < 8; kk++) {
            float ar[8], br[8];
            *(float4*)(ar)     = *(const float4*)&As[s][kk][tr];
            *(float4*)(ar + 4) = *(const float4*)&As[s][kk][tr + 4];
            *(float4*)(br)     = *(const float4*)&Bs[s][kk][tc];
            *(float4*)(br + 4) = *(const float4*)&Bs[s][kk][tc + 4];
#pragma unroll
            for (int i = 0; i < 8; i++)
#pragma unroll
                for (int j = 0; j < 8; j++) acc[i][j] += ar[i] * br[j];
        }
    }

#pragma unroll
    for (int i = 0; i < 8; i++) {
        size_t base = (size_t)(m0 + tr + i) * Ndim + n0 + tc;
        uint32_t H[4], M[4], L[4];
#pragma unroll
        for (int e = 0; e < 4; e++) {
            float2 v = make_float2(acc[i][2 * e] * scl, acc[i][2 * e + 1] * scl);
            split3_f2(v, H[e], M[e], L[e]);
        }
        *(uint4*)&oh[base] = make_uint4(H[0], H[1], H[2], H[3]);
        *(uint4*)&om[base] = make_uint4(M[0], M[1], M[2], M[3]);
        *(uint4*)&ol[base] = make_uint4(L[0], L[1], L[2], L[3]);
    }
}

// ===========================================================================
// bf16 3-term tensor-core GEMM (V projection / Wo projection) — R14-proven.
// ===========================================================================
#define GPITCH 80
#define GTILE  (128 * GPITCH)
#define GSTAGE (4 * GTILE)
#define GSMEM  (3 * GSTAGE)
#define S_AH 0
#define S_AM 1
#define S_BH 2
#define S_BM 3

template <bool VT>
__global__ __launch_bounds__(256) void gemm_bf3_t(
    const __nv_bfloat16* __restrict__ Ah, const __nv_bfloat16* __restrict__ Am,
    const __nv_bfloat16* __restrict__ Bh, const __nv_bfloat16* __restrict__ Bm,
    float* __restrict__ C,
    __nv_bfloat16* __restrict__ CTh, __nv_bfloat16* __restrict__ CTm,
    int Kdim, int Ndim)
{
    extern __shared__ __align__(16) char smem[];

    const int tid = threadIdx.x;
    const int lane = tid & 31, warp = tid >> 5;
    const int m0 = blockIdx.y * 128;
    const int n0 = blockIdx.x * 128;
    const int wm = (warp >> 2) * 64;
    const int wn = (warp & 3) * 32;
    const int lr = tid >> 2;
    const int lq = tid & 3;

    const uint32_t sb = smem_u32(smem);
    const uint32_t aBase = sb + (uint32_t)(wm + (lane & 15)) * GPITCH + (lane >> 4) * 16;
    const uint32_t bBase = sb + (uint32_t)(wn + ((lane >> 4) << 3) + (lane & 7)) * GPITCH
                              + ((lane >> 3) & 1) * 16;

    float acc[4][4][4];
#pragma unroll
    for (int a = 0; a < 4; a++)
#pragma unroll
        for (int b = 0; b < 4; b++)
#pragma unroll
            for (int k = 0; k < 4; k++) acc[a][b][k] = 0.f;

    const int NC = Kdim >> 5;

#define ISSUE_SUB(G, row0, sub, st, k0)                                         \
    {                                                                           \
        _Pragma("unroll")                                                       \
        for (int it = 0; it < 2; it++) {                                        \
            int r = lr + it * 64;                                               \
            cp16(sb + (st) * GSTAGE + (sub) * GTILE + r * GPITCH + lq * 16,     \
                 (const char*)(G) + ((size_t)((row0) + r) * Kdim + (k0)) * 2 + lq * 16); \
        }                                                                       \
    }
#define ISSUE(ch, st)                                                           \
    {                                                                           \
        const int k0_ = (ch) * 32;                                              \
        ISSUE_SUB(Ah, m0, S_AH, st, k0_);                                       \
        ISSUE_SUB(Am, m0, S_AM, st, k0_);                                       \
        ISSUE_SUB(Bh, n0, S_BH, st, k0_);                                       \
        ISSUE_SUB(Bm, n0, S_BM, st, k0_);                                       \
        asm volatile("cp.async.commit_group;");                                 \
    }

    ISSUE(0, 0);
    ISSUE(1, 1);

    for (int c = 0; c < NC; c++) {
        const int st = c % 3;
        if (c + 1 < NC) asm volatile("cp.async.wait_group 1;");
        else            asm volatile("cp.async.wait_group 0;");
        __syncthreads();
        if (c + 2 < NC) ISSUE(c + 2, (c + 2) % 3);

        const uint32_t sah = aBase + st * GSTAGE;
        const uint32_t sbh = bBase + st * GSTAGE + S_BH * GTILE;
#pragma unroll
        for (int ks = 0; ks < 2; ks++) {
            const uint32_t ko = ks * 32;
            uint32_t ah[4][4], am[4], bh[8], bm[8];
#pragma unroll
            for (int mb = 0; mb < 4; mb++)
                ldsm4(ah[mb], sah + S_AH * GTILE + mb * (16 * GPITCH) + ko);
            ldsm4(bh,     sbh + ko);
            ldsm4(bh + 4, sbh + 16 * GPITCH + ko);
#pragma unroll
            for (int mb = 0; mb < 4; mb++)
#pragma unroll
                for (int nb = 0; nb < 4; nb++)
                    mma16816(acc[mb][nb], ah[mb], &bh[nb * 2]);      // h*h
            ldsm4(bm,     sbh + (S_BM - S_BH) * GTILE + ko);
            ldsm4(bm + 4, sbh + (S_BM - S_BH) * GTILE + 16 * GPITCH + ko);
#pragma unroll
            for (int mb = 0; mb < 4; mb++)
#pragma unroll
                for (int nb = 0; nb < 4; nb++)
                    mma16816(acc[mb][nb], ah[mb], &bm[nb * 2]);      // h*m
#pragma unroll
            for (int mb = 0; mb < 4; mb++) {
                ldsm4(am, sah + S_AM * GTILE + mb * (16 * GPITCH) + ko);
#pragma unroll
                for (int nb = 0; nb < 4; nb++)
                    mma16816(acc[mb][nb], am, &bh[nb * 2]);          // m*h
            }
        }
    }

    const int g = lane >> 2, t = lane & 3;
    if (!VT) {
#pragma unroll
        for (int mb = 0; mb < 4; mb++) {
#pragma unroll
            for (int nb = 0; nb < 4; nb++) {
                float* p0 = C + (size_t)(m0 + wm + mb * 16 + g) * Ndim + n0 + wn + nb * 8 + t * 2;
                float* p1 = p0 + 8 * Ndim;
                *(float2*)p0 = make_float2(acc[mb][nb][0], acc[mb][nb][1]);
                *(float2*)p1 = make_float2(acc[mb][nb][2], acc[mb][nb][3]);
            }
        }
    } else {
        __syncthreads();
        float* stage = (float*)smem;
#pragma unroll
        for (int mb = 0; mb < 4; mb++) {
#pragma unroll
            for (int nb = 0; nb < 4; nb++) {
                int row = wm + mb * 16 + g;
                int col = wn + nb * 8 + t * 2;
                stage[row * 132 + col]           = acc[mb][nb][0];
                stage[row * 132 + col + 1]       = acc[mb][nb][1];
                stage[(row + 8) * 132 + col]     = acc[mb][nb][2];
                stage[(row + 8) * 132 + col + 1] = acc[mb][nb][3];
            }
        }
        __syncthreads();
        const int c2 = tid & 127;
        const int half = tid >> 7;
#pragma unroll
        for (int it = 0; it < 8; it++) {
            const int mb0 = half * 64 + it * 8;
            uint32_t hq[4], mq[4];
#pragma unroll
            for (int e = 0; e < 4; e++) {
                float2 v = make_float2(stage[(mb0 + 2 * e) * 132 + c2],
                                       stage[(mb0 + 2 * e + 1) * 132 + c2]);
                hq[e] = bf2h(v);
                mq[e] = bf2m(v, hq[e]);
            }
            size_t idx = (size_t)(n0 + c2) * SEQ + m0 + mb0;
            *(uint4*)&CTh[idx] = make_uint4(hq[0], hq[1], hq[2], hq[3]);
            *(uint4*)&CTm[idx] = make_uint4(mq[0], mq[1], mq[2], mq[3]);
        }
    }
#undef ISSUE
#undef ISSUE_SUB
}

// ===========================================================================
// PV batched GEMM: AO[row, head*64+d] = sum_j P[head][row][j] * VT[head][d][j]
// M-tile 128 x N=64, K-chunks of 32 over [0, mt0+128). bf16 h/m 3-term.
// grid = (SEQ/128, NH). Flip-free path (post-entmax).
// ===========================================================================
#define PV_AH 0
#define PV_AM 10240
#define PV_BH 20480
#define PV_BM 25600
#define PV_STAGE 30720
#define PV_SMEM (3 * PV_STAGE)

__global__ __launch_bounds__(256) void pv_gemm(
    const __nv_bfloat16* __restrict__ Ph, const __nv_bfloat16* __restrict__ Pm,
    const __nv_bfloat16* __restrict__ VTh, const __nv_bfloat16* __restrict__ VTm,
    __nv_bfloat16* __restrict__ AOh, __nv_bfloat16* __restrict__ AOm)
{
    extern __shared__ __align__(16) char smem[];
    const int tid = threadIdx.x;
    const int lane = tid & 31, warp = tid >> 5;
    const int mt0 = blockIdx.x * 128;
    const int hh = blockIdx.y;
    const int wm = warp * 16;

    const char* aH = (const char*)(Ph + ((size_t)hh * SEQ + mt0) * SEQ);
    const char* aM = (const char*)(Pm + ((size_t)hh * SEQ + mt0) * SEQ);
    const char* bH = (const char*)(VTh + (size_t)hh * 64 * SEQ);
    const char* bM = (const char*)(VTm + (size_t)hh * 64 * SEQ);

    const uint32_t sb = smem_u32(smem);
    const uint32_t aBase = sb + (uint32_t)(wm + (lane & 15)) * GPITCH + (lane >> 4) * 16;
    const uint32_t bBase = sb + PV_BH
                         + (uint32_t)(((lane >> 4) << 3) + (lane & 7)) * GPITCH
                         + ((lane >> 3) & 1) * 16;

    const int lr = tid >> 2, lq = tid & 3;
    const int NC = (mt0 + 128) >> 5;

#define PV_ISSUE(ch, st)                                                        \
    {                                                                           \
        const int kb = (ch) * 64;  /* bytes per row offset */                   \
        _Pragma("unroll")                                                       \
        for (int it = 0; it < 2; it++) {                                        \
            int r = lr + it * 64;                                               \
            cp16(sb + (st) * PV_STAGE + PV_AH + r * GPITCH + lq * 16,           \
                 aH + (size_t)r * (SEQ * 2) + kb + lq * 16);                    \
            cp16(sb + (st) * PV_STAGE + PV_AM + r * GPITCH + lq * 16,           \
                 aM + (size_t)r * (SEQ * 2) + kb + lq * 16);                    \
        }                                                                       \
        cp16(sb + (st) * PV_STAGE + PV_BH + lr * GPITCH + lq * 16,              \
             bH + (size_t)lr * (SEQ * 2) + kb + lq * 16);                       \
        cp16(sb + (st) * PV_STAGE + PV_BM + lr * GPITCH + lq * 16,              \
             bM + (size_t)lr * (SEQ * 2) + kb + lq * 16);                       \
        asm volatile("cp.async.commit_group;");                                 \
    }

    float acc[8][4];
#pragma unroll
    for (int nb = 0; nb < 8; nb++)
#pragma unroll
        for (int q = 0; q < 4; q++) acc[nb][q] = 0.f;

    PV_ISSUE(0, 0);
    PV_ISSUE(1, 1);

    for (int c = 0; c < NC; c++) {
        const int st = c % 3;
        if (c + 1 < NC) asm volatile("cp.async.wait_group 1;");
        else            asm volatile("cp.async.wait_group 0;");
        __syncthreads();
        if (c + 2 < NC) PV_ISSUE(c + 2, (c + 2) % 3);

        const uint32_t sa = aBase + st * PV_STAGE;
        const uint32_t sbB = bBase + st * PV_STAGE;
#pragma unroll
        for (int ks = 0; ks < 2; ks++) {
            const uint32_t ko = ks * 32;
            uint32_t ah[4], am[4];
            ldsm4(ah, sa + PV_AH + ko);
            ldsm4(am, sa + (PV_AM - PV_AH) + ko);
#pragma unroll
            for (int j = 0; j < 4; j++) {
                uint32_t bh[4], bm[4];
                ldsm4(bh, sbB + j * (16 * GPITCH) + ko);
                ldsm4(bm, sbB + (PV_BM - PV_BH) + j * (16 * GPITCH) + ko);
                mma16816(acc[j * 2 + 0], ah, &bh[0]);
                mma16816(acc[j * 2 + 1], ah, &bh[2]);
                mma16816(acc[j * 2 + 0], am, &bh[0]);
                mma16816(acc[j * 2 + 1], am, &bh[2]);
                mma16816(acc[j * 2 + 0], ah, &bm[0]);
                mma16816(acc[j * 2 + 1], ah, &bm[2]);
            }
        }
    }

    // epilogue: rows mt0+wm+g (+8), cols nb*8 + t*2 -> AO h/m bf16
    const int g = lane >> 2, t = lane & 3;
#pragma unroll
    for (int nb = 0; nb < 8; nb++) {
        const int col = hh * HD + nb * 8 + t * 2;
        size_t i0 = (size_t)(mt0 + wm + g) * DIM + col;
        size_t i1 = (size_t)(mt0 + wm + g + 8) * DIM + col;
        float2 v0 = make_float2(acc[nb][0], acc[nb][1]);
        float2 v1 = make_float2(acc[nb][2], acc[nb][3]);
        uint32_t h0 = bf2h(v0), h1 = bf2h(v1);
        *(uint32_t*)&AOh[i0] = h0; *(uint32_t*)&AOm[i0] = bf2m(v0, h0);
        *(uint32_t*)&AOh[i1] = h1; *(uint32_t*)&AOm[i1] = bf2m(v1, h1);
    }
#undef PV_ISSUE
}

// ---------------------------------------------------------------------------
// Fused entmax attention: tensor-core scores (R15-proven) + entmax; writes
// P as bf16 h/m to global (zero-padded per row to its 128-block end).
// ---------------------------------------------------------------------------
__global__ __launch_bounds__(256) void attn_kernel(
    const __nv_bfloat16* __restrict__ Qh, const __nv_bfloat16* __restrict__ Qm,
    const __nv_bfloat16* __restrict__ Ql,
    const __nv_bfloat16* __restrict__ Kh, const __nv_bfloat16* __restrict__ Km,
    const __nv_bfloat16* __restrict__ Kl,
    __nv_bfloat16* __restrict__ Ph, __nv_bfloat16* __restrict__ Pm)
{
    extern __shared__ float sm[];
    float* sc = sm;
    char* Qr = (char*)(sm + ROWS * SCP);
    char* Uc = Qr + 3 * 16 * QSP;
    const uint32_t Qb = smem_u32(Qr);
    const uint32_t Ub = smem_u32(Uc);

    const int tid = threadIdx.x;
    const int lane = tid & 31, warp = tid >> 5;
    const int hh = blockIdx.y;
    const int r0 = blockIdx.x * ROWS;
    const int n_max = r0 + ROWS;

    // Q h/m/l tiles
    if (tid < 128) {
        int r = tid >> 3, seg = tid & 7;
        size_t g = (size_t)(r0 + r) * DIM + hh * HD + seg * 8;
        cp16(Qb + 0 * 2304 + r * QSP + seg * 16, Qh + g);
        cp16(Qb + 1 * 2304 + r * QSP + seg * 16, Qm + g);
        cp16(Qb + 2 * 2304 + r * QSP + seg * 16, Ql + g);
    }
    asm volatile("cp.async.commit_group;");
    asm volatile("cp.async.wait_group 0;");
    __syncthreads();

    uint32_t qa[3][4][4];
    {
        const uint32_t aB = Qb + (uint32_t)(lane & 15) * QSP + (lane >> 4) * 16;
#pragma unroll
        for (int ks = 0; ks < 4; ks++) {
            ldsm4(qa[0][ks], aB + 0 * 2304 + ks * 32);
            ldsm4(qa[1][ks], aB + 1 * 2304 + ks * 32);
            ldsm4(qa[2][ks], aB + 2 * 2304 + ks * 32);
        }
    }

    // Phase 2: scores via 8-term MMA, 128-col tiles
    {
        const int wn = warp * 16;
        const uint32_t bB = Ub + (uint32_t)(wn + ((lane >> 4) << 3) + (lane & 7)) * QSP
                               + ((lane >> 3) & 1) * 16;
        const int nt2 = (n_max + 127) >> 7;

        for (int t = 0; t < nt2; t++) {
            const int c0 = t << 7;
            __syncthreads();
#pragma unroll
            for (int s = 0; s < 4; s++) {
                int idx = s * 256 + tid;
                int r = idx >> 3, seg = idx & 7;
                size_t g = (size_t)(c0 + r) * DIM + hh * HD + seg * 8;
                cp16(Ub + OFF_KH + r * QSP + seg * 16, Kh + g);
                cp16(Ub + OFF_KM + r * QSP + seg * 16, Km + g);
                cp16(Ub + OFF_KL + r * QSP + seg * 16, Kl + g);
            }
            asm volatile("cp.async.commit_group;");
            asm volatile("cp.async.wait_group 0;");
            __syncthreads();

            float acc[2][4];
#pragma unroll
            for (int nb = 0; nb < 2; nb++)
#pragma unroll
                for (int q = 0; q < 4; q++) acc[nb][q] = 0.f;

#pragma unroll
            for (int ks = 0; ks < 4; ks++) {
                uint32_t bh[4], bm[4], bl[4];
                ldsm4(bh, bB + OFF_KH + ks * 32);
                ldsm4(bm, bB + OFF_KM + ks * 32);
                ldsm4(bl, bB + OFF_KL + ks * 32);
                mma16816(acc[0], qa[0][ks], &bh[0]); mma16816(acc[1], qa[0][ks], &bh[2]);
                mma16816(acc[0], qa[1][ks], &bh[0]); mma16816(acc[1], qa[1][ks], &bh[2]);
                mma16816(acc[0], qa[0][ks], &bm[0]); mma16816(acc[1], qa[0][ks], &bm[2]);
                mma16816(acc[0], qa[1][ks], &bm[0]); mma16816(acc[1], qa[1][ks], &bm[2]);
                mma16816(acc[0], qa[0][ks], &bl[0]); mma16816(acc[1], qa[0][ks], &bl[2]);
                mma16816(acc[0], qa[2][ks], &bh[0]); mma16816(acc[1], qa[2][ks], &bh[2]);
                mma16816(acc[0], qa[1][ks], &bl[0]); mma16816(acc[1], qa[1][ks], &bl[2]);
                mma16816(acc[0], qa[2][ks], &bm[0]); mma16816(acc[1], qa[2][ks], &bm[2]);
            }

            const int g = lane >> 2, t2 = (lane & 3) * 2;
#pragma unroll
            for (int nb = 0; nb < 2; nb++) {
                const int col = c0 + wn + nb * 8 + t2;
                *(float2*)&sc[(size_t)g * SCP + col] =
                    make_float2(acc[nb][0], acc[nb][1]);
                *(float2*)&sc[(size_t)(g + 8) * SCP + col] =
                    make_float2(acc[nb][2], acc[nb][3]);
            }
        }
    }
    __syncthreads();

    // Phase 3: entmax per row; write P bf16 h/m to global, zero-pad
    {
        const int w = warp;
        const int fill_end = (r0 & ~127) + 128;
        const __nv_bfloat16 bz = __float2bfloat16_rn(0.f);

        for (int rr = w; rr < ROWS; rr += 8) {
            const int n = r0 + rr + 1;
            float* srow = sc + (size_t)rr * SCP;
            const float4* srow4 = (const float4*)srow;
            const int nv = n >> 2;
            const int ntail = nv << 2;

            float ssum = 0.f;
            for (int q = lane; q < nv; q += 32) {
                float4 v = srow4[q];
                ssum += (v.x + v.y) + (v.z + v.w);
            }
            for (int j = ntail + lane; j < n; j += 32) ssum += srow[j];
#pragma unroll
            for (int o = 16; o; o >>= 1) ssum += __shfl_xor_sync(0xFFFFFFFFu, ssum, o);

            int k = n;
            float tau = (ssum - 1.0f) / (float)n;
            for (int it = 0; it < SEQ; ++it) {
                float sa = 0.f; int ca = 0;
                for (int q = lane; q < nv; q += 32) {
                    float4 v = srow4[q];
                    if (v.x > tau) { sa += v.x; ca++; }
                    if (v.y > tau) { sa += v.y; ca++; }
                    if (v.z > tau) { sa += v.z; ca++; }
                    if (v.w > tau) { sa += v.w; ca++; }
                }
                for (int j = ntail + lane; j < n; j += 32) {
                    float v = srow[j];
                    if (v > tau) { sa += v; ca++; }
                }
#pragma unroll
                for (int o = 16; o; o >>= 1) {
                    sa += __shfl_xor_sync(0xFFFFFFFFu, sa, o);
                    ca += __shfl_xor_sync(0xFFFFFFFFu, ca, o);
                }
                if (ca == k) break;
                k = ca;
                tau = (sa - 1.0f) / (float)ca;
            }

            const float tau_star = (ssum - 1.0f) / (float)k;  // reference quirk: TOTAL sum

            float psum = 0.f;
            for (int q = lane; q < nv; q += 32) {
                float4 v = srow4[q];
                psum += fmaxf(v.x - tau_star, 0.f) + fmaxf(v.y - tau_star, 0.f)
                      + fmaxf(v.z - tau_star, 0.f) + fmaxf(v.w - tau_star, 0.f);
            }
            for (int j = ntail + lane; j < n; j += 32)
                psum += fmaxf(srow[j] - tau_star, 0.f);
#pragma unroll
            for (int o = 16; o; o >>= 1) psum += __shfl_xor_sync(0xFFFFFFFFu, psum, o);
            const float inv = 1.0f / (psum + 1e-10f);

            __nv_bfloat16* ph = Ph + ((size_t)hh * SEQ + r0 + rr) * SEQ;
            __nv_bfloat16* pmw = Pm + ((size_t)hh * SEQ + r0 + rr) * SEQ;
            for (int q = lane; q < nv; q += 32) {
                float4 v = srow4[q];
                float2 a = make_float2(fmaxf(v.x - tau_star, 0.f) * inv,
                                       fmaxf(v.y - tau_star, 0.f) * inv);
                float2 b = make_float2(fmaxf(v.z - tau_star, 0.f) * inv,
                                       fmaxf(v.w - tau_star, 0.f) * inv);
                uint32_t ha = bf2h(a), hb2 = bf2h(b);
                *(uint32_t*)&ph[q * 4]      = ha;
                *(uint32_t*)&ph[q * 4 + 2]  = hb2;
                *(uint32_t*)&pmw[q * 4]     = bf2m(a, ha);
                *(uint32_t*)&pmw[q * 4 + 2] = bf2m(b, hb2);
            }
            for (int j = ntail + lane; j < n; j += 32) {
                float p = fmaxf(srow[j] - tau_star, 0.f) * inv;
                __nv_bfloat16 h = __float2bfloat16_rn(p);
                ph[j] = h;
                pmw[j] = __float2bfloat16_rn(p - __bfloat162float(h));
            }
            for (int j = n + lane; j < fill_end; j += 32) {
                ph[j] = bz;
                pmw[j] = bz;
            }
        }
    }
}

// ---------------------------------------------------------------------------
extern "C" void kernel_launch(void* const* d_in, const int* in_sizes, int n_in,
                              void* d_out, int out_size)
{
    const float* x  = (const float*)d_in[0];
    const float* Wq = (const float*)d_in[1];
    const float* Wk = (const float*)d_in[2];
    const float* Wv = (const float*)d_in[3];
    const float* Wo = (const float*)d_in[4];
    float* out = (float*)d_out;

    __nv_bfloat16 *qh, *qm, *ql, *kh, *km, *kl, *vth, *vtm;
    __nv_bfloat16 *xh, *xm, *aoh, *aom, *wvh, *wvm, *woh, *wom, *ph, *pm;
    cudaGetSymbolAddress((void**)&qh,  g_qh);  cudaGetSymbolAddress((void**)&qm,  g_qm);
    cudaGetSymbolAddress((void**)&ql,  g_ql);
    cudaGetSymbolAddress((void**)&kh,  g_kh);  cudaGetSymbolAddress((void**)&km,  g_km);
    cudaGetSymbolAddress((void**)&kl,  g_kl);
    cudaGetSymbolAddress((void**)&vth, g_vth); cudaGetSymbolAddress((void**)&vtm, g_vtm);
    cudaGetSymbolAddress((void**)&xh,  g_xh);  cudaGetSymbolAddress((void**)&xm,  g_xm);
    cudaGetSymbolAddress((void**)&aoh, g_aoh); cudaGetSymbolAddress((void**)&aom, g_aom);
    cudaGetSymbolAddress((void**)&wvh, g_wvh); cudaGetSymbolAddress((void**)&wvm, g_wvm);
    cudaGetSymbolAddress((void**)&woh, g_woh); cudaGetSymbolAddress((void**)&wom, g_wom);
    cudaGetSymbolAddress((void**)&ph,  g_ph);  cudaGetSymbolAddress((void**)&pm,  g_pm);

    const size_t attn_smem = (size_t)ROWS * SCP * 4 + 3 * 16 * QSP + 3 * 18432;
    cudaFuncSetAttribute(attn_kernel, cudaFuncAttributeMaxDynamicSharedMemorySize,
                         (int)attn_smem);
    cudaFuncSetAttribute(pv_gemm, cudaFuncAttributeMaxDynamicSharedMemorySize, PV_SMEM);
    cudaFuncSetAttribute(gemm_bf3_t<false>, cudaFuncAttributeMaxDynamicSharedMemorySize, GSMEM);
    cudaFuncSetAttribute(gemm_bf3_t<true>,  cudaFuncAttributeMaxDynamicSharedMemorySize, GSMEM);

    const int n4x = SEQ * DIM / 4;
    const int n4w = DIM * DIM / 4;

    split2<<<n4x / 256, 256>>>(x,  xh,  xm,  n4x);
    split2<<<n4w / 256, 256>>>(Wv, wvh, wvm, n4w);
    split2<<<n4w / 256, 256>>>(Wo, woh, wom, n4w);

    {   // Q,K projections: fp32 SIMT (REQUIRED: flip-sensitive K=1024 path)
        dim3 grid(DIM / 128, SEQ / 128, 2);
        sgemm_split<<<grid, 256>>>(x, Wq, Wk, qh, qm, ql, kh, km, kl, DIM, DIM);
    }
    {   // V projection: bf16x3 tensor cores, transposed bf16 h/m output
        dim3 grid(DIM / 128, SEQ / 128, 1);
        gemm_bf3_t<true><<<grid, 256, GSMEM>>>(xh, xm, wvh, wvm,
                                               nullptr, vth, vtm, DIM, DIM);
    }
    {   // scores + entmax -> P bf16 h/m
        dim3 grid(SEQ / ROWS, NH);
        attn_kernel<<<grid, 256, attn_smem>>>(qh, qm, ql, kh, km, kl, ph, pm);
    }
    {   // PV batched GEMM (flip-free)
        dim3 grid(SEQ / 128, NH);
        pv_gemm<<<grid, 256, PV_SMEM>>>(ph, pm, vth, vtm, aoh, aom);
    }
    {   // output projection: bf16x3 tensor cores
        dim3 grid(DIM / 128, SEQ / 128, 1);
        gemm_bf3_t<false><<<grid, 256, GSMEM>>>(aoh, aom, woh, wom,
                                                out, nullptr, nullptr, DIM, DIM);
    }
}